// round 9
// baseline (speedup 1.0000x reference)
#include <cuda_runtime.h>
#include <cstdint>

#define Bdim 4
#define Tdim 256
#define Sdim 256
#define Ddim 512

// Scratch (allocation-free rule: __device__ globals)
__device__ float g_wq[Bdim * Tdim * Ddim];    // 2 MB
__device__ float g_uh[Bdim * Sdim * Ddim];    // 2 MB
__device__ float g_sc[Bdim * Tdim * Sdim];    // 1 MB raw scores
__device__ float g_pre1[Bdim * Sdim * Ddim];  // 2 MB  ctx @ Wout_top
__device__ float g_pre2[Bdim * Tdim * Ddim];  // 2 MB  output @ Wout_bot + bout

__device__ __forceinline__ float tanh_fast(float x) {
    float y;
    asm("tanh.approx.f32 %0, %1;" : "=f"(y) : "f"(x));
    return y;
}

__device__ __forceinline__ uint32_t f2tf32(float x) {
    uint32_t y;
    asm("cvt.rna.tf32.f32 %0, %1;" : "=r"(y) : "f"(x));
    return y;
}

__device__ __forceinline__ void mma_tf32(float* d, const uint32_t* a,
                                         const uint32_t* b) {
    asm volatile(
        "mma.sync.aligned.m16n8k8.row.col.f32.tf32.tf32.f32 "
        "{%0,%1,%2,%3}, {%4,%5,%6,%7}, {%8,%9}, {%0,%1,%2,%3};"
        : "+f"(d[0]), "+f"(d[1]), "+f"(d[2]), "+f"(d[3])
        : "r"(a[0]), "r"(a[1]), "r"(a[2]), "r"(a[3]), "r"(b[0]), "r"(b[1]));
}

#define CP16(dst, src) \
    asm volatile("cp.async.cg.shared.global [%0], [%1], 16;" \
                 :: "r"(dst), "l"(src) : "memory")
#define CP_COMMIT() asm volatile("cp.async.commit_group;" ::: "memory")
#define CP_WAIT2()  asm volatile("cp.async.wait_group 2;" ::: "memory")
#define CP_WAIT1()  asm volatile("cp.async.wait_group 1;" ::: "memory")

#define STAGES 4
#define LDA 20
#define LDB 72
#define ABYTES (64 * LDA * 4)
#define BBYTES (16 * LDB * 4)

// ---------------------------------------------------------------------------
// 128-thread core: 64x64 tile, 4 warps (2x2), warp tile 32x32. (gemm4)
// ---------------------------------------------------------------------------
__device__ __forceinline__ void gemm_core(
    const float* __restrict__ A, int lda,
    const float* __restrict__ B, int ldb, int K,
    const float* __restrict__ bias, float* __restrict__ C, int N,
    int m0, int n0)
{
    __shared__ float As[STAGES][64 * LDA];
    __shared__ float Bs[STAGES][16 * LDB];

    const int tid = threadIdx.x;
    const int wid = tid >> 5;
    const int lane = tid & 31;
    const int g = lane >> 2;
    const int tig = lane & 3;
    const int warp_m = wid >> 1;
    const int warp_n = wid & 1;

    const int ar = tid >> 1;
    const int ak = (tid & 1) << 3;
    const int br = tid >> 3;
    const int bc = (tid & 7) << 3;

    uint32_t as_s = (uint32_t)__cvta_generic_to_shared(&As[0][0]);
    uint32_t bs_s = (uint32_t)__cvta_generic_to_shared(&Bs[0][0]);

    const int NT = K >> 4;

    float acc[2][4][4];
#pragma unroll
    for (int i = 0; i < 2; i++)
#pragma unroll
        for (int j = 0; j < 4; j++)
#pragma unroll
            for (int q = 0; q < 4; q++) acc[i][j][q] = 0.f;

    auto issue = [&](int stage, int kt) {
        const int kg = kt << 4;
        const float* s0 = A + (long)(m0 + ar) * lda + kg + ak;
        uint32_t d0 = as_s + stage * ABYTES + (ar * LDA + ak) * 4;
        CP16(d0, s0);
        CP16(d0 + 16, s0 + 4);
        const float* sb = B + (long)(kg + br) * ldb + n0 + bc;
        uint32_t db = bs_s + stage * BBYTES + (br * LDB + bc) * 4;
        CP16(db, sb);
        CP16(db + 16, sb + 4);
    };

#pragma unroll
    for (int p = 0; p < STAGES - 1; p++) {
        if (p < NT) issue(p, p);
        CP_COMMIT();
    }

    for (int t = 0; t < NT; t++) {
        const int st = t & (STAGES - 1);
        CP_WAIT2();
        __syncthreads();

        if (t + STAGES - 1 < NT) issue((t + STAGES - 1) & (STAGES - 1), t + STAGES - 1);
        CP_COMMIT();

        const float* as = As[st];
        const float* bs = Bs[st];
        const int mb = warp_m * 32;
        const int nb = warp_n * 32;
#pragma unroll
        for (int ks = 0; ks < 2; ks++) {
            const int k0 = ks << 3;
            uint32_t a[2][4], b[4][2];
#pragma unroll
            for (int im = 0; im < 2; im++) {
                const float* ap = as + (mb + im * 16 + g) * LDA;
                a[im][0] = f2tf32(ap[k0 + tig]);
                a[im][1] = f2tf32(ap[8 * LDA + k0 + tig]);
                a[im][2] = f2tf32(ap[k0 + tig + 4]);
                a[im][3] = f2tf32(ap[8 * LDA + k0 + tig + 4]);
            }
#pragma unroll
            for (int in = 0; in < 4; in++) {
                const int nc = nb + in * 8 + g;
                b[in][0] = f2tf32(bs[(k0 + tig) * LDB + nc]);
                b[in][1] = f2tf32(bs[(k0 + tig + 4) * LDB + nc]);
            }
#pragma unroll
            for (int im = 0; im < 2; im++)
#pragma unroll
                for (int in = 0; in < 4; in++)
                    mma_tf32(acc[im][in], a[im], b[in]);
        }
        __syncthreads();
    }

    const int mb = warp_m * 32;
    const int nb = warp_n * 32;
#pragma unroll
    for (int im = 0; im < 2; im++) {
#pragma unroll
        for (int in = 0; in < 4; in++) {
            const int row = m0 + mb + im * 16 + g;
            const int col = n0 + nb + in * 8 + tig * 2;
            float bx = 0.f, by = 0.f;
            if (bias) { bx = bias[col]; by = bias[col + 1]; }
            float2 o0 = make_float2(acc[im][in][0] + bx, acc[im][in][1] + by);
            float2 o1 = make_float2(acc[im][in][2] + bx, acc[im][in][3] + by);
            *(float2*)&C[(long)row * N + col] = o0;
            *(float2*)&C[(long)(row + 8) * N + col] = o1;
        }
    }
}

// Four independent 1024x512x512 jobs selected by blockIdx.z
struct Job {
    const float* A;
    const float* B;
    const float* bias;
    float* C;
};

__global__ __launch_bounds__(128) void gemm4(Job j0, Job j1, Job j2, Job j3)
{
    Job j = (blockIdx.z == 0) ? j0 : (blockIdx.z == 1) ? j1
          : (blockIdx.z == 2) ? j2 : j3;
    gemm_core(j.A, Ddim, j.B, Ddim, Ddim, j.bias, j.C, Ddim,
              blockIdx.y * 64, blockIdx.x * 64);
}

// ---------------------------------------------------------------------------
// score[b,t,s] = sum_d v[d] * tanh(wq[b,t,d] + uh[b,s,d])
// ---------------------------------------------------------------------------
__global__ __launch_bounds__(256) void score_kernel(
    const float* __restrict__ wq, const float* __restrict__ uh,
    const float* __restrict__ v, float* __restrict__ sc)
{
    __shared__ float Aq[32][33];
    __shared__ float Au[32][33];
    __shared__ float vs[32];

    const int b = blockIdx.z;
    const int t0 = blockIdx.y * 32;
    const int s0 = blockIdx.x * 32;
    const int tid = threadIdx.x;
    const int tx = tid & 15, ty = tid >> 4;

    const float* wqb = wq + ((long)b * Tdim + t0) * Ddim;
    const float* uhb = uh + ((long)b * Sdim + s0) * Ddim;

    const int lr = tid >> 3;
    const int lc = (tid & 7) << 2;

    float acc00 = 0.f, acc01 = 0.f, acc10 = 0.f, acc11 = 0.f;

    for (int d0 = 0; d0 < Ddim; d0 += 32) {
        float4 q = *(const float4*)&wqb[(long)lr * Ddim + d0 + lc];
        Aq[lc + 0][lr] = q.x;
        Aq[lc + 1][lr] = q.y;
        Aq[lc + 2][lr] = q.z;
        Aq[lc + 3][lr] = q.w;
        float4 u = *(const float4*)&uhb[(long)lr * Ddim + d0 + lc];
        Au[lc + 0][lr] = u.x;
        Au[lc + 1][lr] = u.y;
        Au[lc + 2][lr] = u.z;
        Au[lc + 3][lr] = u.w;
        if (tid < 32) vs[tid] = v[d0 + tid];
        __syncthreads();

#pragma unroll
        for (int dk = 0; dk < 32; dk++) {
            float vv = vs[dk];
            float a0 = Aq[dk][ty * 2 + 0];
            float a1 = Aq[dk][ty * 2 + 1];
            float u0 = Au[dk][tx * 2 + 0];
            float u1 = Au[dk][tx * 2 + 1];
            acc00 += vv * tanh_fast(a0 + u0);
            acc01 += vv * tanh_fast(a0 + u1);
            acc10 += vv * tanh_fast(a1 + u0);
            acc11 += vv * tanh_fast(a1 + u1);
        }
        __syncthreads();
    }

    float* scp = sc + ((long)b * Tdim + t0) * Sdim + s0;
    scp[(long)(ty * 2 + 0) * Sdim + tx * 2 + 0] = acc00;
    scp[(long)(ty * 2 + 0) * Sdim + tx * 2 + 1] = acc01;
    scp[(long)(ty * 2 + 1) * Sdim + tx * 2 + 0] = acc10;
    scp[(long)(ty * 2 + 1) * Sdim + tx * 2 + 1] = acc11;
}

// ---------------------------------------------------------------------------
// Fused masked-softmax + final GEMM.
// Block: (d-block 64, t-block 64, batch). 256 threads (8 warps, 2m x 4n).
// Phase 1: load raw scores [64 x 256] into smem (stride 260 -> conflict-free
//          mma A-fragment loads: bank = (4g + tig) % 32, all lanes distinct).
// Phase 2: reference masked softmax per row in smem; blockIdx.x==0 also
//          writes attn to d_out.
// Phase 3: out = attn_smem @ pre1 + pre2 via mma.sync (A from smem,
//          pre1 via 3-stage cp.async).
// ---------------------------------------------------------------------------
#define SLD 260
#define NBSTG 3

__global__ __launch_bounds__(256) void fin_fused(
    const float* __restrict__ sc, const int* __restrict__ mask,
    const float* __restrict__ pre1, const float* __restrict__ pre2,
    float* __restrict__ out, float* __restrict__ attn_out)
{
    extern __shared__ float dyn[];
    float* Ssm = dyn;                        // 64 * 260
    float* keepsm = dyn + 64 * SLD;          // 256
    float* Bs = keepsm + 256;                // NBSTG * 16 * LDB

    const int b = blockIdx.z;
    const int t0 = blockIdx.y * 64;
    const int n0 = blockIdx.x * 64;
    const int tid = threadIdx.x;
    const int wid = tid >> 5;
    const int lane = tid & 31;
    const int g = lane >> 2;
    const int tig = lane & 3;
    const int warp_m = wid >> 2;   // 0..1
    const int warp_n = wid & 3;    // 0..3

    const float* pre1b = pre1 + (long)b * Sdim * Ddim;
    const float* pre2b = pre2 + (long)b * Tdim * Ddim;
    float* outb = out + (long)b * Tdim * Ddim;

    // ---- Phase 1: scores -> smem ----
    {
        const int r = tid >> 2;
        const int c0 = (tid & 3) << 6;
        const float* srow = sc + ((long)(b * Tdim + t0 + r)) * Sdim + c0;
        float* drow = Ssm + r * SLD + c0;
#pragma unroll
        for (int i = 0; i < 16; i++) {
            float4 vv = *(const float4*)(srow + i * 4);
            *(float4*)(drow + i * 4) = vv;
        }
        if (tid < 256) keepsm[tid] = 1.0f - (float)mask[b * Sdim + tid];
    }
    __syncthreads();

    // ---- Phase 2: masked softmax per row (warp w: rows w, w+8, ..., w+56) ----
    float* arow_base = attn_out ? attn_out + ((long)(b * Tdim + t0)) * Sdim : nullptr;
    const bool wr_attn = (blockIdx.x == 0) && (attn_out != nullptr);
#pragma unroll
    for (int j = 0; j < 8; j++) {
        const int r = wid + j * 8;
        float* rp = Ssm + r * SLD;
        float x[8];
        float m = -1e30f;
#pragma unroll
        for (int i = 0; i < 8; i++) {
            x[i] = rp[i * 32 + lane];
            m = fmaxf(m, x[i]);
        }
#pragma unroll
        for (int o = 16; o > 0; o >>= 1)
            m = fmaxf(m, __shfl_xor_sync(0xffffffffu, m, o));
        float e[8];
        float sum = 0.f;
#pragma unroll
        for (int i = 0; i < 8; i++) {
            e[i] = __expf(x[i] - m) * keepsm[i * 32 + lane];
            sum += e[i];
        }
#pragma unroll
        for (int o = 16; o > 0; o >>= 1)
            sum += __shfl_xor_sync(0xffffffffu, sum, o);
        const float inv = 1.0f / sum;
#pragma unroll
        for (int i = 0; i < 8; i++) {
            const float a = e[i] * inv;
            rp[i * 32 + lane] = a;
            if (wr_attn) arow_base[(long)r * Sdim + i * 32 + lane] = a;
        }
    }
    __syncthreads();

    // ---- Phase 3: GEMM out[64x64] = Ssm[64x256] @ pre1[256x64] + pre2 ----
    const int br = tid >> 4;          // 0..15
    const int bc = (tid & 15) << 2;   // 0..60
    uint32_t bs_s = (uint32_t)__cvta_generic_to_shared(Bs);

    auto issueB = [&](int stage, int kt) {
        const int kg = kt << 4;
        const float* sb = pre1b + (long)(kg + br) * Ddim + n0 + bc;
        uint32_t db = bs_s + stage * BBYTES + (br * LDB + bc) * 4;
        CP16(db, sb);
    };

    issueB(0, 0); CP_COMMIT();
    issueB(1, 1); CP_COMMIT();

    float acc[2][2][4];
#pragma unroll
    for (int i = 0; i < 2; i++)
#pragma unroll
        for (int j = 0; j < 2; j++)
#pragma unroll
            for (int q = 0; q < 4; q++) acc[i][j][q] = 0.f;

    const int NT = Sdim >> 4;  // 16
    const int mb = warp_m * 32;
    const int nb = warp_n * 16;

    for (int t = 0; t < NT; t++) {
        const int st = t % NBSTG;
        CP_WAIT1();
        __syncthreads();

        if (t + 2 < NT) issueB((t + 2) % NBSTG, t + 2);
        CP_COMMIT();

        const float* bs = Bs + st * (16 * LDB);
        const int kg = t << 4;
#pragma unroll
        for (int ks = 0; ks < 2; ks++) {
            const int k0 = ks << 3;
            uint32_t a[2][4], bb[2][2];
#pragma unroll
            for (int im = 0; im < 2; im++) {
                const float* ap = Ssm + (mb + im * 16 + g) * SLD + kg + k0 + tig;
                a[im][0] = f2tf32(ap[0]);
                a[im][1] = f2tf32(ap[8 * SLD]);
                a[im][2] = f2tf32(ap[4]);
                a[im][3] = f2tf32(ap[8 * SLD + 4]);
            }
#pragma unroll
            for (int in = 0; in < 2; in++) {
                const int nc = nb + in * 8 + g;
                bb[in][0] = f2tf32(bs[(k0 + tig) * LDB + nc]);
                bb[in][1] = f2tf32(bs[(k0 + tig + 4) * LDB + nc]);
            }
#pragma unroll
            for (int im = 0; im < 2; im++)
#pragma unroll
                for (int in = 0; in < 2; in++)
                    mma_tf32(acc[im][in], a[im], bb[in]);
        }
        __syncthreads();
    }

#pragma unroll
    for (int im = 0; im < 2; im++) {
#pragma unroll
        for (int in = 0; in < 2; in++) {
            const int row = t0 + mb + im * 16 + g;
            const int col = n0 + nb + in * 8 + tig * 2;
            const float2 r0 = *(const float2*)&pre2b[(long)row * Ddim + col];
            const float2 r1 = *(const float2*)&pre2b[(long)(row + 8) * Ddim + col];
            float2 o0 = make_float2(acc[im][in][0] + r0.x, acc[im][in][1] + r0.y);
            float2 o1 = make_float2(acc[im][in][2] + r1.x, acc[im][in][3] + r1.y);
            *(float2*)&outb[(long)row * Ddim + col] = o0;
            *(float2*)&outb[(long)(row + 8) * Ddim + col] = o1;
        }
    }
}

// ---------------------------------------------------------------------------
extern "C" void kernel_launch(void* const* d_in, const int* in_sizes, int n_in,
                              void* d_out, int out_size)
{
    const float* out_in = (const float*)d_in[0];  // (B,T,D)
    const float* ctx    = (const float*)d_in[1];  // (B,S,D)
    const int*   mask   = (const int*)d_in[2];    // (B,S)
    const float* Wq     = (const float*)d_in[3];  // (D,D)
    const float* bq     = (const float*)d_in[4];  // (D,)
    const float* Wc     = (const float*)d_in[5];  // (D,D)
    const float* v      = (const float*)d_in[6];  // (D,)
    const float* Wout   = (const float*)d_in[7];  // (2D,D)
    const float* bout   = (const float*)d_in[8];  // (D,)

    float *p_wq, *p_uh, *p_sc, *p_pre1, *p_pre2;
    cudaGetSymbolAddress((void**)&p_wq, g_wq);
    cudaGetSymbolAddress((void**)&p_uh, g_uh);
    cudaGetSymbolAddress((void**)&p_sc, g_sc);
    cudaGetSymbolAddress((void**)&p_pre1, g_pre1);
    cudaGetSymbolAddress((void**)&p_pre2, g_pre2);

    const long BTD = (long)Bdim * Tdim * Ddim;  // 524288
    const long BTS = (long)Bdim * Tdim * Sdim;  // 262144
    float* out_f = (float*)d_out;
    float* attn_out = ((long)out_size >= BTD + BTS) ? (out_f + BTD) : nullptr;

    // 1) Four fused 1024x512x512 GEMMs
    Job j0{out_in, Wq, bq, p_wq};
    Job j1{ctx, Wc, nullptr, p_uh};
    Job j2{ctx, Wout, nullptr, p_pre1};
    Job j3{out_in, Wout + (long)Ddim * Ddim, bout, p_pre2};
    gemm4<<<dim3(Ddim / 64, (Bdim * Tdim) / 64, 4), 128>>>(j0, j1, j2, j3);

    // 2) raw scores
    score_kernel<<<dim3(Sdim / 32, Tdim / 32, Bdim), 256>>>(p_wq, p_uh, v, p_sc);

    // 3) fused masked-softmax + final GEMM (+ attn output)
    const int dyn_bytes = (64 * SLD + 256 + NBSTG * 16 * LDB) * 4;  // 81408
    static bool attr_set = false;
    if (!attr_set) {
        cudaFuncSetAttribute(fin_fused,
                             cudaFuncAttributeMaxDynamicSharedMemorySize,
                             dyn_bytes);
        attr_set = true;
    }
    fin_fused<<<dim3(Ddim / 64, Tdim / 64, Bdim), 256, dyn_bytes>>>(
        p_sc, mask, p_pre1, p_pre2, out_f, attn_out);
}

// round 10
// speedup vs baseline: 1.0482x; 1.0482x over previous
#include <cuda_runtime.h>
#include <cstdint>

#define Bdim 4
#define Tdim 256
#define Sdim 256
#define Ddim 512

// Scratch (allocation-free rule: __device__ globals)
__device__ float g_wq[Bdim * Tdim * Ddim];    // 2 MB
__device__ float g_uh[Bdim * Sdim * Ddim];    // 2 MB
__device__ float g_sc[Bdim * Tdim * Sdim];    // 1 MB (scores, then attn)
__device__ float g_pre1[Bdim * Sdim * Ddim];  // 2 MB  ctx @ Wout_top
__device__ float g_pre2[Bdim * Tdim * Ddim];  // 2 MB  output @ Wout_bot + bout

__device__ __forceinline__ float tanh_fast(float x) {
    float y;
    asm("tanh.approx.f32 %0, %1;" : "=f"(y) : "f"(x));
    return y;
}

__device__ __forceinline__ uint32_t f2tf32(float x) {
    uint32_t y;
    asm("cvt.rna.tf32.f32 %0, %1;" : "=r"(y) : "f"(x));
    return y;
}

__device__ __forceinline__ void mma_tf32(float* d, const uint32_t* a,
                                         const uint32_t* b) {
    asm volatile(
        "mma.sync.aligned.m16n8k8.row.col.f32.tf32.tf32.f32 "
        "{%0,%1,%2,%3}, {%4,%5,%6,%7}, {%8,%9}, {%0,%1,%2,%3};"
        : "+f"(d[0]), "+f"(d[1]), "+f"(d[2]), "+f"(d[3])
        : "r"(a[0]), "r"(a[1]), "r"(a[2]), "r"(a[3]), "r"(b[0]), "r"(b[1]));
}

#define CP16(dst, src) \
    asm volatile("cp.async.cg.shared.global [%0], [%1], 16;" \
                 :: "r"(dst), "l"(src) : "memory")
#define CP_COMMIT() asm volatile("cp.async.commit_group;" ::: "memory")
#define CP_WAIT2()  asm volatile("cp.async.wait_group 2;" ::: "memory")
#define CP_WAIT1()  asm volatile("cp.async.wait_group 1;" ::: "memory")

#define LDA 20
#define LDB 72

// ---------------------------------------------------------------------------
// gemm4: four independent 1024x512x512 jobs. 256 threads, CTA tile 128x64,
// 8 warps (4m x 2n), warp tile 32x32, BK=16, 3-stage cp.async.
// 256 CTAs total -> ~1.7 CTA/SM, ~14 resident warps/SM (latency hiding).
// ---------------------------------------------------------------------------
#define G4STG 3
#define G4_AB (128 * LDA * 4)
#define G4_BB (16 * LDB * 4)

struct Job {
    const float* A;
    const float* B;
    const float* bias;
    float* C;
};

__global__ __launch_bounds__(256) void gemm4(Job j0, Job j1, Job j2, Job j3)
{
    __shared__ float As[G4STG][128 * LDA];  // 30720 B
    __shared__ float Bs[G4STG][16 * LDB];   // 13824 B

    Job j = (blockIdx.z == 0) ? j0 : (blockIdx.z == 1) ? j1
          : (blockIdx.z == 2) ? j2 : j3;

    const int tid = threadIdx.x;
    const int wid = tid >> 5;
    const int lane = tid & 31;
    const int g = lane >> 2;
    const int tig = lane & 3;
    const int warp_m = wid >> 1;   // 0..3
    const int warp_n = wid & 1;    // 0..1

    const int m0 = blockIdx.y * 128;
    const int n0 = blockIdx.x * 64;

    const int ar = tid >> 1;          // 0..127
    const int ak = (tid & 1) << 3;    // 0 or 8
    const int br = tid >> 4;          // 0..15
    const int bc = (tid & 15) << 2;   // 0..60

    uint32_t as_s = (uint32_t)__cvta_generic_to_shared(&As[0][0]);
    uint32_t bs_s = (uint32_t)__cvta_generic_to_shared(&Bs[0][0]);

    const int NT = Ddim >> 4;  // 32

    float acc[2][4][4];
#pragma unroll
    for (int i = 0; i < 2; i++)
#pragma unroll
        for (int jj = 0; jj < 4; jj++)
#pragma unroll
            for (int q = 0; q < 4; q++) acc[i][jj][q] = 0.f;

    auto issue = [&](int stage, int kt) {
        const int kg = kt << 4;
        const float* s0 = j.A + (long)(m0 + ar) * Ddim + kg + ak;
        uint32_t d0 = as_s + stage * G4_AB + (ar * LDA + ak) * 4;
        CP16(d0, s0);
        CP16(d0 + 16, s0 + 4);
        const float* sb = j.B + (long)(kg + br) * Ddim + n0 + bc;
        uint32_t db = bs_s + stage * G4_BB + (br * LDB + bc) * 4;
        CP16(db, sb);
    };

    issue(0, 0); CP_COMMIT();
    issue(1, 1); CP_COMMIT();

    for (int t = 0; t < NT; t++) {
        const int st = t % G4STG;
        CP_WAIT1();
        __syncthreads();

        if (t + 2 < NT) issue((t + 2) % G4STG, t + 2);
        CP_COMMIT();

        const float* as = As[st];
        const float* bs = Bs[st];
        const int mb = warp_m * 32;
        const int nb = warp_n * 32;
#pragma unroll
        for (int ks = 0; ks < 2; ks++) {
            const int k0 = ks << 3;
            uint32_t a[2][4], b[4][2];
#pragma unroll
            for (int im = 0; im < 2; im++) {
                const float* ap = as + (mb + im * 16 + g) * LDA;
                a[im][0] = f2tf32(ap[k0 + tig]);
                a[im][1] = f2tf32(ap[8 * LDA + k0 + tig]);
                a[im][2] = f2tf32(ap[k0 + tig + 4]);
                a[im][3] = f2tf32(ap[8 * LDA + k0 + tig + 4]);
            }
#pragma unroll
            for (int in = 0; in < 4; in++) {
                const int nc = nb + in * 8 + g;
                b[in][0] = f2tf32(bs[(k0 + tig) * LDB + nc]);
                b[in][1] = f2tf32(bs[(k0 + tig + 4) * LDB + nc]);
            }
#pragma unroll
            for (int im = 0; im < 2; im++)
#pragma unroll
                for (int in = 0; in < 4; in++)
                    mma_tf32(acc[im][in], a[im], b[in]);
        }
        __syncthreads();
    }

    const int mb = warp_m * 32;
    const int nb = warp_n * 32;
#pragma unroll
    for (int im = 0; im < 2; im++) {
#pragma unroll
        for (int in = 0; in < 4; in++) {
            const int row = m0 + mb + im * 16 + g;
            const int col = n0 + nb + in * 8 + tig * 2;
            float bx = 0.f, by = 0.f;
            if (j.bias) { bx = j.bias[col]; by = j.bias[col + 1]; }
            float2 o0 = make_float2(acc[im][in][0] + bx, acc[im][in][1] + by);
            float2 o1 = make_float2(acc[im][in][2] + bx, acc[im][in][3] + by);
            *(float2*)&j.C[(long)row * Ddim + col] = o0;
            *(float2*)&j.C[(long)(row + 8) * Ddim + col] = o1;
        }
    }
}

// ---------------------------------------------------------------------------
// gemm_fin: out[b] = attn[b] @ pre1[b] + pre2[b]  (256x512, K=256 per batch)
// 256 threads, 64x64 tile, 8 warps (2m x 4n), warp tile 32x16, 4 stages.
// ---------------------------------------------------------------------------
#define FSTG 4
#define F_AB (64 * LDA * 4)
#define F_BB (16 * LDB * 4)

__global__ __launch_bounds__(256) void gemm_fin(
    const float* __restrict__ attn, const float* __restrict__ pre1,
    const float* __restrict__ pre2, float* __restrict__ out)
{
    __shared__ float As[FSTG][64 * LDA];
    __shared__ float Bs[FSTG][16 * LDB];

    const int z = blockIdx.z;
    const float* A = attn + (long)z * Tdim * Sdim;
    const float* B = pre1 + (long)z * Sdim * Ddim;
    const float* addend = pre2 + (long)z * Tdim * Ddim;
    float* C = out + (long)z * Tdim * Ddim;

    const int tid = threadIdx.x;
    const int wid = tid >> 5;
    const int lane = tid & 31;
    const int g = lane >> 2;
    const int tig = lane & 3;
    const int warp_m = wid >> 2;
    const int warp_n = wid & 3;

    const int m0 = blockIdx.y * 64;
    const int n0 = blockIdx.x * 64;

    const int ar = tid >> 2;
    const int ak = (tid & 3) << 2;
    const int br = tid >> 4;
    const int bc = (tid & 15) << 2;

    uint32_t as_s = (uint32_t)__cvta_generic_to_shared(&As[0][0]);
    uint32_t bs_s = (uint32_t)__cvta_generic_to_shared(&Bs[0][0]);

    const int NT = Sdim >> 4;  // 16

    float acc[2][2][4];
#pragma unroll
    for (int i = 0; i < 2; i++)
#pragma unroll
        for (int jj = 0; jj < 2; jj++)
#pragma unroll
            for (int q = 0; q < 4; q++) acc[i][jj][q] = 0.f;

    auto issue = [&](int stage, int kt) {
        const int kg = kt << 4;
        const float* s0 = A + (long)(m0 + ar) * Sdim + kg + ak;
        uint32_t d0 = as_s + stage * F_AB + (ar * LDA + ak) * 4;
        CP16(d0, s0);
        const float* sb = B + (long)(kg + br) * Ddim + n0 + bc;
        uint32_t db = bs_s + stage * F_BB + (br * LDB + bc) * 4;
        CP16(db, sb);
    };

#pragma unroll
    for (int p = 0; p < FSTG - 1; p++) {
        if (p < NT) issue(p, p);
        CP_COMMIT();
    }

    for (int t = 0; t < NT; t++) {
        const int st = t & (FSTG - 1);
        CP_WAIT2();
        __syncthreads();

        if (t + FSTG - 1 < NT) issue((t + FSTG - 1) & (FSTG - 1), t + FSTG - 1);
        CP_COMMIT();

        const float* as = As[st];
        const float* bs = Bs[st];
        const int mb = warp_m * 32;
        const int nb = warp_n * 16;
#pragma unroll
        for (int ks = 0; ks < 2; ks++) {
            const int k0 = ks << 3;
            uint32_t a[2][4], b[2][2];
#pragma unroll
            for (int im = 0; im < 2; im++) {
                const float* ap = as + (mb + im * 16 + g) * LDA;
                a[im][0] = f2tf32(ap[k0 + tig]);
                a[im][1] = f2tf32(ap[8 * LDA + k0 + tig]);
                a[im][2] = f2tf32(ap[k0 + tig + 4]);
                a[im][3] = f2tf32(ap[8 * LDA + k0 + tig + 4]);
            }
#pragma unroll
            for (int in = 0; in < 2; in++) {
                const int nc = nb + in * 8 + g;
                b[in][0] = f2tf32(bs[(k0 + tig) * LDB + nc]);
                b[in][1] = f2tf32(bs[(k0 + tig + 4) * LDB + nc]);
            }
#pragma unroll
            for (int im = 0; im < 2; im++)
#pragma unroll
                for (int in = 0; in < 2; in++)
                    mma_tf32(acc[im][in], a[im], b[in]);
        }
        __syncthreads();
    }

    const int mb = warp_m * 32;
    const int nb = warp_n * 16;
#pragma unroll
    for (int im = 0; im < 2; im++) {
#pragma unroll
        for (int in = 0; in < 2; in++) {
            const int row = m0 + mb + im * 16 + g;
            const int col = n0 + nb + in * 8 + tig * 2;
            const float2 r0 = *(const float2*)&addend[(long)row * Ddim + col];
            const float2 r1 = *(const float2*)&addend[(long)(row + 8) * Ddim + col];
            float2 o0 = make_float2(acc[im][in][0] + r0.x, acc[im][in][1] + r0.y);
            float2 o1 = make_float2(acc[im][in][2] + r1.x, acc[im][in][3] + r1.y);
            *(float2*)&C[(long)row * Ddim + col] = o0;
            *(float2*)&C[(long)(row + 8) * Ddim + col] = o1;
        }
    }
}

// ---------------------------------------------------------------------------
// score[b,t,s] = sum_d v[d] * tanh(wq[b,t,d] + uh[b,s,d])
// ---------------------------------------------------------------------------
__global__ __launch_bounds__(256) void score_kernel(
    const float* __restrict__ wq, const float* __restrict__ uh,
    const float* __restrict__ v, float* __restrict__ sc)
{
    __shared__ float Aq[32][33];
    __shared__ float Au[32][33];
    __shared__ float vs[32];

    const int b = blockIdx.z;
    const int t0 = blockIdx.y * 32;
    const int s0 = blockIdx.x * 32;
    const int tid = threadIdx.x;
    const int tx = tid & 15, ty = tid >> 4;

    const float* wqb = wq + ((long)b * Tdim + t0) * Ddim;
    const float* uhb = uh + ((long)b * Sdim + s0) * Ddim;

    const int lr = tid >> 3;
    const int lc = (tid & 7) << 2;

    float acc00 = 0.f, acc01 = 0.f, acc10 = 0.f, acc11 = 0.f;

    for (int d0 = 0; d0 < Ddim; d0 += 32) {
        float4 q = *(const float4*)&wqb[(long)lr * Ddim + d0 + lc];
        Aq[lc + 0][lr] = q.x;
        Aq[lc + 1][lr] = q.y;
        Aq[lc + 2][lr] = q.z;
        Aq[lc + 3][lr] = q.w;
        float4 u = *(const float4*)&uhb[(long)lr * Ddim + d0 + lc];
        Au[lc + 0][lr] = u.x;
        Au[lc + 1][lr] = u.y;
        Au[lc + 2][lr] = u.z;
        Au[lc + 3][lr] = u.w;
        if (tid < 32) vs[tid] = v[d0 + tid];
        __syncthreads();

#pragma unroll
        for (int dk = 0; dk < 32; dk++) {
            float vv = vs[dk];
            float a0 = Aq[dk][ty * 2 + 0];
            float a1 = Aq[dk][ty * 2 + 1];
            float u0 = Au[dk][tx * 2 + 0];
            float u1 = Au[dk][tx * 2 + 1];
            acc00 += vv * tanh_fast(a0 + u0);
            acc01 += vv * tanh_fast(a0 + u1);
            acc10 += vv * tanh_fast(a1 + u0);
            acc11 += vv * tanh_fast(a1 + u1);
        }
        __syncthreads();
    }

    float* scp = sc + ((long)b * Tdim + t0) * Sdim + s0;
    scp[(long)(ty * 2 + 0) * Sdim + tx * 2 + 0] = acc00;
    scp[(long)(ty * 2 + 0) * Sdim + tx * 2 + 1] = acc01;
    scp[(long)(ty * 2 + 1) * Sdim + tx * 2 + 0] = acc10;
    scp[(long)(ty * 2 + 1) * Sdim + tx * 2 + 1] = acc11;
}

// ---------------------------------------------------------------------------
// Masked softmax: warp-per-row, 8 rows/block (reference semantics).
// ---------------------------------------------------------------------------
__global__ __launch_bounds__(256) void softmax_kernel(
    float* __restrict__ sc, const int* __restrict__ mask,
    float* __restrict__ attn_out)
{
    const int warp = threadIdx.x >> 5;
    const int lane = threadIdx.x & 31;
    const int row = blockIdx.x * 8 + warp;
    const int b = row >> 8;

    float* rp = sc + (long)row * Sdim;
    const int* mp = mask + b * Sdim;

    float x[8];
    float m = -1e30f;
#pragma unroll
    for (int i = 0; i < 8; i++) {
        x[i] = rp[i * 32 + lane];
        m = fmaxf(m, x[i]);
    }
#pragma unroll
    for (int o = 16; o > 0; o >>= 1)
        m = fmaxf(m, __shfl_xor_sync(0xffffffffu, m, o));

    float e[8];
    float sum = 0.f;
#pragma unroll
    for (int i = 0; i < 8; i++) {
        float keep = 1.0f - (float)mp[i * 32 + lane];
        e[i] = __expf(x[i] - m) * keep;
        sum += e[i];
    }
#pragma unroll
    for (int o = 16; o > 0; o >>= 1)
        sum += __shfl_xor_sync(0xffffffffu, sum, o);

    const float inv = 1.0f / sum;
    float* ap = attn_out ? attn_out + (long)row * Sdim : nullptr;
#pragma unroll
    for (int i = 0; i < 8; i++) {
        float a = e[i] * inv;
        rp[i * 32 + lane] = a;
        if (ap) ap[i * 32 + lane] = a;
    }
}

// ---------------------------------------------------------------------------
extern "C" void kernel_launch(void* const* d_in, const int* in_sizes, int n_in,
                              void* d_out, int out_size)
{
    const float* out_in = (const float*)d_in[0];  // (B,T,D)
    const float* ctx    = (const float*)d_in[1];  // (B,S,D)
    const int*   mask   = (const int*)d_in[2];    // (B,S)
    const float* Wq     = (const float*)d_in[3];  // (D,D)
    const float* bq     = (const float*)d_in[4];  // (D,)
    const float* Wc     = (const float*)d_in[5];  // (D,D)
    const float* v      = (const float*)d_in[6];  // (D,)
    const float* Wout   = (const float*)d_in[7];  // (2D,D)
    const float* bout   = (const float*)d_in[8];  // (D,)

    float *p_wq, *p_uh, *p_sc, *p_pre1, *p_pre2;
    cudaGetSymbolAddress((void**)&p_wq, g_wq);
    cudaGetSymbolAddress((void**)&p_uh, g_uh);
    cudaGetSymbolAddress((void**)&p_sc, g_sc);
    cudaGetSymbolAddress((void**)&p_pre1, g_pre1);
    cudaGetSymbolAddress((void**)&p_pre2, g_pre2);

    const long BTD = (long)Bdim * Tdim * Ddim;  // 524288
    const long BTS = (long)Bdim * Tdim * Sdim;  // 262144
    float* out_f = (float*)d_out;
    float* attn_out = ((long)out_size >= BTD + BTS) ? (out_f + BTD) : nullptr;

    // 1) Four fused 1024x512x512 GEMMs (256 CTAs x 256 threads)
    Job j0{out_in, Wq, bq, p_wq};
    Job j1{ctx, Wc, nullptr, p_uh};
    Job j2{ctx, Wout, nullptr, p_pre1};
    Job j3{out_in, Wout + (long)Ddim * Ddim, bout, p_pre2};
    gemm4<<<dim3(Ddim / 64, (Bdim * Tdim) / 128, 4), 256>>>(j0, j1, j2, j3);

    // 2) score
    score_kernel<<<dim3(Sdim / 32, Tdim / 32, Bdim), 256>>>(p_wq, p_uh, v, p_sc);

    // 3) masked softmax (attn in-place in g_sc, also to d_out attn region)
    softmax_kernel<<<(Bdim * Tdim) / 8, 256>>>(p_sc, mask, attn_out);

    // 4) out = attn @ pre1 + pre2   (batched 256x512, K=256)
    gemm_fin<<<dim3(Ddim / 64, Tdim / 64, Bdim), 256>>>(p_sc, p_pre1, p_pre2, out_f);
}

// round 11
// speedup vs baseline: 1.1034x; 1.0527x over previous
#include <cuda_runtime.h>
#include <cstdint>

#define Bdim 4
#define Tdim 256
#define Sdim 256
#define Ddim 512

// Scratch (allocation-free rule: __device__ globals)
__device__ float g_wq[Bdim * Tdim * Ddim];    // 2 MB
__device__ float g_uh[Bdim * Sdim * Ddim];    // 2 MB
__device__ float g_sc[Bdim * Tdim * Sdim];    // 1 MB (scores, then attn)
__device__ float g_pre1[Bdim * Sdim * Ddim];  // 2 MB  ctx @ Wout_top
__device__ float g_pre2[Bdim * Tdim * Ddim];  // 2 MB  output @ Wout_bot + bout

__device__ __forceinline__ float tanh_fast(float x) {
    float y;
    asm("tanh.approx.f32 %0, %1;" : "=f"(y) : "f"(x));
    return y;
}

// Raw fp32 bits as tf32 operand: tensor core uses tf32-significant bits only
// (truncation). Saves the cvt.rna.tf32 issue slots in the mainloop.
__device__ __forceinline__ uint32_t raw_tf32(float x) {
    return __float_as_uint(x);
}

__device__ __forceinline__ void mma_tf32(float* d, const uint32_t* a,
                                         const uint32_t* b) {
    asm volatile(
        "mma.sync.aligned.m16n8k8.row.col.f32.tf32.tf32.f32 "
        "{%0,%1,%2,%3}, {%4,%5,%6,%7}, {%8,%9}, {%0,%1,%2,%3};"
        : "+f"(d[0]), "+f"(d[1]), "+f"(d[2]), "+f"(d[3])
        : "r"(a[0]), "r"(a[1]), "r"(a[2]), "r"(a[3]), "r"(b[0]), "r"(b[1]));
}

#define CP16(dst, src) \
    asm volatile("cp.async.cg.shared.global [%0], [%1], 16;" \
                 :: "r"(dst), "l"(src) : "memory")
#define CP_COMMIT() asm volatile("cp.async.commit_group;" ::: "memory")
#define CP_WAIT2()  asm volatile("cp.async.wait_group 2;" ::: "memory")
#define CP_WAIT1()  asm volatile("cp.async.wait_group 1;" ::: "memory")

#define LDA 20
#define LDB 72

// ---------------------------------------------------------------------------
// gemm4: four independent 1024x512x512 jobs. 256 threads, CTA tile 128x64,
// 8 warps (4m x 2n), warp tile 32x32, BK=16, 3-stage cp.async,
// ONE barrier per mainloop iteration.
// ---------------------------------------------------------------------------
#define G4STG 3
#define G4_AB (128 * LDA * 4)
#define G4_BB (16 * LDB * 4)

struct Job {
    const float* A;
    const float* B;
    const float* bias;
    float* C;
};

__global__ __launch_bounds__(256) void gemm4(Job j0, Job j1, Job j2, Job j3)
{
    __shared__ float As[G4STG][128 * LDA];
    __shared__ float Bs[G4STG][16 * LDB];

    Job j = (blockIdx.z == 0) ? j0 : (blockIdx.z == 1) ? j1
          : (blockIdx.z == 2) ? j2 : j3;

    const int tid = threadIdx.x;
    const int wid = tid >> 5;
    const int lane = tid & 31;
    const int g = lane >> 2;
    const int tig = lane & 3;
    const int warp_m = wid >> 1;
    const int warp_n = wid & 1;

    const int m0 = blockIdx.y * 128;
    const int n0 = blockIdx.x * 64;

    const int ar = tid >> 1;
    const int ak = (tid & 1) << 3;
    const int br = tid >> 4;
    const int bc = (tid & 15) << 2;

    uint32_t as_s = (uint32_t)__cvta_generic_to_shared(&As[0][0]);
    uint32_t bs_s = (uint32_t)__cvta_generic_to_shared(&Bs[0][0]);

    const int NT = Ddim >> 4;  // 32

    float acc[2][4][4];
#pragma unroll
    for (int i = 0; i < 2; i++)
#pragma unroll
        for (int jj = 0; jj < 4; jj++)
#pragma unroll
            for (int q = 0; q < 4; q++) acc[i][jj][q] = 0.f;

    auto issue = [&](int stage, int kt) {
        const int kg = kt << 4;
        const float* s0 = j.A + (long)(m0 + ar) * Ddim + kg + ak;
        uint32_t d0 = as_s + stage * G4_AB + (ar * LDA + ak) * 4;
        CP16(d0, s0);
        CP16(d0 + 16, s0 + 4);
        const float* sb = j.B + (long)(kg + br) * Ddim + n0 + bc;
        uint32_t db = bs_s + stage * G4_BB + (br * LDB + bc) * 4;
        CP16(db, sb);
    };

    issue(0, 0); CP_COMMIT();
    issue(1, 1); CP_COMMIT();

    for (int t = 0; t < NT; t++) {
        const int st = t % G4STG;
        CP_WAIT1();
        __syncthreads();   // single barrier: data for t visible; compute(t-1) done

        if (t + 2 < NT) issue((t + 2) % G4STG, t + 2);
        CP_COMMIT();

        const float* as = As[st];
        const float* bs = Bs[st];
        const int mb = warp_m * 32;
        const int nb = warp_n * 32;
#pragma unroll
        for (int ks = 0; ks < 2; ks++) {
            const int k0 = ks << 3;
            uint32_t a[2][4], b[4][2];
#pragma unroll
            for (int im = 0; im < 2; im++) {
                const float* ap = as + (mb + im * 16 + g) * LDA;
                a[im][0] = raw_tf32(ap[k0 + tig]);
                a[im][1] = raw_tf32(ap[8 * LDA + k0 + tig]);
                a[im][2] = raw_tf32(ap[k0 + tig + 4]);
                a[im][3] = raw_tf32(ap[8 * LDA + k0 + tig + 4]);
            }
#pragma unroll
            for (int in = 0; in < 4; in++) {
                const int nc = nb + in * 8 + g;
                b[in][0] = raw_tf32(bs[(k0 + tig) * LDB + nc]);
                b[in][1] = raw_tf32(bs[(k0 + tig + 4) * LDB + nc]);
            }
#pragma unroll
            for (int im = 0; im < 2; im++)
#pragma unroll
                for (int in = 0; in < 4; in++)
                    mma_tf32(acc[im][in], a[im], b[in]);
        }
    }

    __syncthreads();
    const int mb = warp_m * 32;
    const int nb = warp_n * 32;
#pragma unroll
    for (int im = 0; im < 2; im++) {
#pragma unroll
        for (int in = 0; in < 4; in++) {
            const int row = m0 + mb + im * 16 + g;
            const int col = n0 + nb + in * 8 + tig * 2;
            float bx = 0.f, by = 0.f;
            if (j.bias) { bx = j.bias[col]; by = j.bias[col + 1]; }
            float2 o0 = make_float2(acc[im][in][0] + bx, acc[im][in][1] + by);
            float2 o1 = make_float2(acc[im][in][2] + bx, acc[im][in][3] + by);
            *(float2*)&j.C[(long)row * Ddim + col] = o0;
            *(float2*)&j.C[(long)(row + 8) * Ddim + col] = o1;
        }
    }
}

// ---------------------------------------------------------------------------
// gemm_fin: out[b] = attn[b] @ pre1[b] + pre2[b]  (256x512, K=256 per batch)
// 256 threads, 64x64 tile, 8 warps (2m x 4n), warp tile 32x16, 4 stages,
// single barrier per iteration.
// ---------------------------------------------------------------------------
#define FSTG 4
#define F_AB (64 * LDA * 4)
#define F_BB (16 * LDB * 4)

__global__ __launch_bounds__(256) void gemm_fin(
    const float* __restrict__ attn, const float* __restrict__ pre1,
    const float* __restrict__ pre2, float* __restrict__ out)
{
    __shared__ float As[FSTG][64 * LDA];
    __shared__ float Bs[FSTG][16 * LDB];

    const int z = blockIdx.z;
    const float* A = attn + (long)z * Tdim * Sdim;
    const float* B = pre1 + (long)z * Sdim * Ddim;
    const float* addend = pre2 + (long)z * Tdim * Ddim;
    float* C = out + (long)z * Tdim * Ddim;

    const int tid = threadIdx.x;
    const int wid = tid >> 5;
    const int lane = tid & 31;
    const int g = lane >> 2;
    const int tig = lane & 3;
    const int warp_m = wid >> 2;
    const int warp_n = wid & 3;

    const int m0 = blockIdx.y * 64;
    const int n0 = blockIdx.x * 64;

    const int ar = tid >> 2;
    const int ak = (tid & 3) << 2;
    const int br = tid >> 4;
    const int bc = (tid & 15) << 2;

    uint32_t as_s = (uint32_t)__cvta_generic_to_shared(&As[0][0]);
    uint32_t bs_s = (uint32_t)__cvta_generic_to_shared(&Bs[0][0]);

    const int NT = Sdim >> 4;  // 16

    float acc[2][2][4];
#pragma unroll
    for (int i = 0; i < 2; i++)
#pragma unroll
        for (int jj = 0; jj < 2; jj++)
#pragma unroll
            for (int q = 0; q < 4; q++) acc[i][jj][q] = 0.f;

    auto issue = [&](int stage, int kt) {
        const int kg = kt << 4;
        const float* s0 = A + (long)(m0 + ar) * Sdim + kg + ak;
        uint32_t d0 = as_s + stage * F_AB + (ar * LDA + ak) * 4;
        CP16(d0, s0);
        const float* sb = B + (long)(kg + br) * Ddim + n0 + bc;
        uint32_t db = bs_s + stage * F_BB + (br * LDB + bc) * 4;
        CP16(db, sb);
    };

#pragma unroll
    for (int p = 0; p < FSTG - 1; p++) {
        if (p < NT) issue(p, p);
        CP_COMMIT();
    }

    for (int t = 0; t < NT; t++) {
        const int st = t & (FSTG - 1);
        CP_WAIT2();
        __syncthreads();   // single barrier per iteration

        if (t + FSTG - 1 < NT) issue((t + FSTG - 1) & (FSTG - 1), t + FSTG - 1);
        CP_COMMIT();

        const float* as = As[st];
        const float* bs = Bs[st];
        const int mb = warp_m * 32;
        const int nb = warp_n * 16;
#pragma unroll
        for (int ks = 0; ks < 2; ks++) {
            const int k0 = ks << 3;
            uint32_t a[2][4], b[2][2];
#pragma unroll
            for (int im = 0; im < 2; im++) {
                const float* ap = as + (mb + im * 16 + g) * LDA;
                a[im][0] = raw_tf32(ap[k0 + tig]);
                a[im][1] = raw_tf32(ap[8 * LDA + k0 + tig]);
                a[im][2] = raw_tf32(ap[k0 + tig + 4]);
                a[im][3] = raw_tf32(ap[8 * LDA + k0 + tig + 4]);
            }
#pragma unroll
            for (int in = 0; in < 2; in++) {
                const int nc = nb + in * 8 + g;
                b[in][0] = raw_tf32(bs[(k0 + tig) * LDB + nc]);
                b[in][1] = raw_tf32(bs[(k0 + tig + 4) * LDB + nc]);
            }
#pragma unroll
            for (int im = 0; im < 2; im++)
#pragma unroll
                for (int in = 0; in < 2; in++)
                    mma_tf32(acc[im][in], a[im], b[in]);
        }
    }

    __syncthreads();
    const int mb = warp_m * 32;
    const int nb = warp_n * 16;
#pragma unroll
    for (int im = 0; im < 2; im++) {
#pragma unroll
        for (int in = 0; in < 2; in++) {
            const int row = m0 + mb + im * 16 + g;
            const int col = n0 + nb + in * 8 + tig * 2;
            const float2 r0 = *(const float2*)&addend[(long)row * Ddim + col];
            const float2 r1 = *(const float2*)&addend[(long)(row + 8) * Ddim + col];
            float2 o0 = make_float2(acc[im][in][0] + r0.x, acc[im][in][1] + r0.y);
            float2 o1 = make_float2(acc[im][in][2] + r1.x, acc[im][in][3] + r1.y);
            *(float2*)&C[(long)row * Ddim + col] = o0;
            *(float2*)&C[(long)(row + 8) * Ddim + col] = o1;
        }
    }
}

// ---------------------------------------------------------------------------
// score[b,t,s] = sum_d v[d] * tanh(wq[b,t,d] + uh[b,s,d])
// ---------------------------------------------------------------------------
__global__ __launch_bounds__(256) void score_kernel(
    const float* __restrict__ wq, const float* __restrict__ uh,
    const float* __restrict__ v, float* __restrict__ sc)
{
    __shared__ float Aq[32][33];
    __shared__ float Au[32][33];
    __shared__ float vs[32];

    const int b = blockIdx.z;
    const int t0 = blockIdx.y * 32;
    const int s0 = blockIdx.x * 32;
    const int tid = threadIdx.x;
    const int tx = tid & 15, ty = tid >> 4;

    const float* wqb = wq + ((long)b * Tdim + t0) * Ddim;
    const float* uhb = uh + ((long)b * Sdim + s0) * Ddim;

    const int lr = tid >> 3;
    const int lc = (tid & 7) << 2;

    float acc00 = 0.f, acc01 = 0.f, acc10 = 0.f, acc11 = 0.f;

    for (int d0 = 0; d0 < Ddim; d0 += 32) {
        float4 q = *(const float4*)&wqb[(long)lr * Ddim + d0 + lc];
        Aq[lc + 0][lr] = q.x;
        Aq[lc + 1][lr] = q.y;
        Aq[lc + 2][lr] = q.z;
        Aq[lc + 3][lr] = q.w;
        float4 u = *(const float4*)&uhb[(long)lr * Ddim + d0 + lc];
        Au[lc + 0][lr] = u.x;
        Au[lc + 1][lr] = u.y;
        Au[lc + 2][lr] = u.z;
        Au[lc + 3][lr] = u.w;
        if (tid < 32) vs[tid] = v[d0 + tid];
        __syncthreads();

#pragma unroll
        for (int dk = 0; dk < 32; dk++) {
            float vv = vs[dk];
            float a0 = Aq[dk][ty * 2 + 0];
            float a1 = Aq[dk][ty * 2 + 1];
            float u0 = Au[dk][tx * 2 + 0];
            float u1 = Au[dk][tx * 2 + 1];
            acc00 += vv * tanh_fast(a0 + u0);
            acc01 += vv * tanh_fast(a0 + u1);
            acc10 += vv * tanh_fast(a1 + u0);
            acc11 += vv * tanh_fast(a1 + u1);
        }
        __syncthreads();
    }

    float* scp = sc + ((long)b * Tdim + t0) * Sdim + s0;
    scp[(long)(ty * 2 + 0) * Sdim + tx * 2 + 0] = acc00;
    scp[(long)(ty * 2 + 0) * Sdim + tx * 2 + 1] = acc01;
    scp[(long)(ty * 2 + 1) * Sdim + tx * 2 + 0] = acc10;
    scp[(long)(ty * 2 + 1) * Sdim + tx * 2 + 1] = acc11;
}

// ---------------------------------------------------------------------------
// Masked softmax: warp-per-row, 8 rows/block (reference semantics).
// ---------------------------------------------------------------------------
__global__ __launch_bounds__(256) void softmax_kernel(
    float* __restrict__ sc, const int* __restrict__ mask,
    float* __restrict__ attn_out)
{
    const int warp = threadIdx.x >> 5;
    const int lane = threadIdx.x & 31;
    const int row = blockIdx.x * 8 + warp;
    const int b = row >> 8;

    float* rp = sc + (long)row * Sdim;
    const int* mp = mask + b * Sdim;

    float x[8];
    float m = -1e30f;
#pragma unroll
    for (int i = 0; i < 8; i++) {
        x[i] = rp[i * 32 + lane];
        m = fmaxf(m, x[i]);
    }
#pragma unroll
    for (int o = 16; o > 0; o >>= 1)
        m = fmaxf(m, __shfl_xor_sync(0xffffffffu, m, o));

    float e[8];
    float sum = 0.f;
#pragma unroll
    for (int i = 0; i < 8; i++) {
        float keep = 1.0f - (float)mp[i * 32 + lane];
        e[i] = __expf(x[i] - m) * keep;
        sum += e[i];
    }
#pragma unroll
    for (int o = 16; o > 0; o >>= 1)
        sum += __shfl_xor_sync(0xffffffffu, sum, o);

    const float inv = 1.0f / sum;
    float* ap = attn_out ? attn_out + (long)row * Sdim : nullptr;
#pragma unroll
    for (int i = 0; i < 8; i++) {
        float a = e[i] * inv;
        rp[i * 32 + lane] = a;
        if (ap) ap[i * 32 + lane] = a;
    }
}

// ---------------------------------------------------------------------------
extern "C" void kernel_launch(void* const* d_in, const int* in_sizes, int n_in,
                              void* d_out, int out_size)
{
    const float* out_in = (const float*)d_in[0];  // (B,T,D)
    const float* ctx    = (const float*)d_in[1];  // (B,S,D)
    const int*   mask   = (const int*)d_in[2];    // (B,S)
    const float* Wq     = (const float*)d_in[3];  // (D,D)
    const float* bq     = (const float*)d_in[4];  // (D,)
    const float* Wc     = (const float*)d_in[5];  // (D,D)
    const float* v      = (const float*)d_in[6];  // (D,)
    const float* Wout   = (const float*)d_in[7];  // (2D,D)
    const float* bout   = (const float*)d_in[8];  // (D,)

    float *p_wq, *p_uh, *p_sc, *p_pre1, *p_pre2;
    cudaGetSymbolAddress((void**)&p_wq, g_wq);
    cudaGetSymbolAddress((void**)&p_uh, g_uh);
    cudaGetSymbolAddress((void**)&p_sc, g_sc);
    cudaGetSymbolAddress((void**)&p_pre1, g_pre1);
    cudaGetSymbolAddress((void**)&p_pre2, g_pre2);

    const long BTD = (long)Bdim * Tdim * Ddim;  // 524288
    const long BTS = (long)Bdim * Tdim * Sdim;  // 262144
    float* out_f = (float*)d_out;
    float* attn_out = ((long)out_size >= BTD + BTS) ? (out_f + BTD) : nullptr;

    // 1) Four fused 1024x512x512 GEMMs
    Job j0{out_in, Wq, bq, p_wq};
    Job j1{ctx, Wc, nullptr, p_uh};
    Job j2{ctx, Wout, nullptr, p_pre1};
    Job j3{out_in, Wout + (long)Ddim * Ddim, bout, p_pre2};
    gemm4<<<dim3(Ddim / 64, (Bdim * Tdim) / 128, 4), 256>>>(j0, j1, j2, j3);

    // 2) score
    score_kernel<<<dim3(Sdim / 32, Tdim / 32, Bdim), 256>>>(p_wq, p_uh, v, p_sc);

    // 3) masked softmax (attn in-place in g_sc, also to d_out attn region)
    softmax_kernel<<<(Bdim * Tdim) / 8, 256>>>(p_sc, mask, attn_out);

    // 4) out = attn @ pre1 + pre2   (batched 256x512, K=256)
    gemm_fin<<<dim3(Ddim / 64, Tdim / 64, Bdim), 256>>>(p_sc, p_pre1, p_pre2, out_f);
}